// round 2
// baseline (speedup 1.0000x reference)
#include <cuda_runtime.h>

// LatticeSnake: B=16 batches, N=48 acids, K=7 window, PAD=3, LP=195.
// Reference scatters 48 acid points + 47 midpoint "inter" points into a 195^3
// lattice (last-write-wins, inters scattered after acids), then extracts a 7^3
// window at each acid's idx2 position and masks it by mask[n].
//
// Lattice-free: every coordinate fits in 8 bits, so a 3-D scatter position
// packs into one 24-bit key. One CTA per window: build the 95 (key,value)
// candidates in shared memory in scatter order (-1 key = dropped), then each
// of the 343 window cells does a forward overwrite-on-match sweep over all 95
// candidates — reproducing the in-order scatter (last write wins) exactly.
//
// NOTE: mask is read as int32 — the harness materializes the JAX bool input
// as 4-byte ints (reading it as 1-byte bools zeroed ~75% of masks in R1,
// rel_err ~= 1.0).

#define BATCH   16
#define NACID   48
#define KWIN    7
#define PADW    3
#define CELLS   (KWIN * KWIN * KWIN)   // 343
#define NCAND   (2 * NACID - 1)        // 95
#define NTHREADS 384

__global__ __launch_bounds__(NTHREADS)
void lattice_snake_kernel(const float* __restrict__ acids,
                          const int* __restrict__ mask,
                          const int* __restrict__ idx,
                          float* __restrict__ out)
{
    __shared__ int2 cand[NCAND];   // .x = packed position key (-1 = dropped), .y = value bits

    const int win = blockIdx.x;        // 0 .. B*N-1
    const int b   = win / NACID;
    const int n   = win % NACID;
    const int t   = threadIdx.x;

    const int*   idxb = idx   + b * NACID * 3;
    const float* ab   = acids + b * NACID;
    const int*   mb   = mask  + b * NACID;

    // ---- build candidate list (scatter order: acids 0..47, then inters 0..46) ----
    if (t < NACID) {
        // acid i: lattice pos = 2*idx + 94 + PAD  (each dim)
        const int i = t;
        const int x = 2 * idxb[3 * i + 0] + 94 + PADW;
        const int y = 2 * idxb[3 * i + 1] + 94 + PADW;
        const int z = 2 * idxb[3 * i + 2] + 94 + PADW;
        const int key = mb[i] ? ((x << 16) | (y << 8) | z) : -1;
        cand[i] = make_int2(key, __float_as_int(ab[i]));
    } else if (t < NCAND) {
        // inter j: pos = (idx2_j + idx2_{j+1})/2 + PAD = idx_j + idx_{j+1} + 94 + PAD
        const int j = t - NACID;   // 0 .. 46
        const int x = idxb[3 * j + 0] + idxb[3 * (j + 1) + 0] + 94 + PADW;
        const int y = idxb[3 * j + 1] + idxb[3 * (j + 1) + 1] + 94 + PADW;
        const int z = idxb[3 * j + 2] + idxb[3 * (j + 1) + 2] + 94 + PADW;
        const int key = mb[j + 1] ? ((x << 16) | (y << 8) | z) : -1;
        const float v = ab[j] + ab[j + 1] + 1.0f;
        cand[t] = make_int2(key, __float_as_int(v));
    }
    __syncthreads();

    if (t >= CELLS) return;

    // window base (lattice coords; no clamping needed: 94 <= idx2 <= 188 = LP-K)
    const int bx = 2 * idxb[3 * n + 0] + 94;
    const int by = 2 * idxb[3 * n + 1] + 94;
    const int bz = 2 * idxb[3 * n + 2] + 94;
    const float mscale = mb[n] ? 1.0f : 0.0f;

    const int d0 = t / 49;
    const int r  = t - d0 * 49;
    const int d1 = r / 7;
    const int d2 = r - d1 * 7;
    const int key = ((bx + d0) << 16) | ((by + d1) << 8) | (bz + d2);

    // forward sweep, overwrite on match == in-order scatter, last write wins
    float v = 0.0f;
#pragma unroll
    for (int i = 0; i < NCAND; ++i) {
        const int2 c = cand[i];          // LDS.64 broadcast (all lanes same addr)
        if (c.x == key) v = __int_as_float(c.y);
    }

    out[win * CELLS + t] = v * mscale;
}

extern "C" void kernel_launch(void* const* d_in, const int* in_sizes, int n_in,
                              void* d_out, int out_size)
{
    const float* acids = (const float*)d_in[0];   // (B, N) float32
    const int*   mask  = (const int*)d_in[1];     // (B, N) bool -> int32
    const int*   idx   = (const int*)d_in[2];     // (B, N, 3) int32
    float*       out   = (float*)d_out;           // (B, N, 7,7,7, 1) float32

    lattice_snake_kernel<<<BATCH * NACID, NTHREADS>>>(acids, mask, idx, out);
}

// round 3
// speedup vs baseline: 1.3092x; 1.3092x over previous
#include <cuda_runtime.h>

// LatticeSnake: B=16, N=48, K=7, PAD=3, LP=195.
// Reference scatters 48 acid points + 47 midpoint "inter" points into a 195^3
// lattice (in-order, last-write-wins, inters after acids), then extracts a 7^3
// window at each acid's idx2 and masks by mask[n].
//
// R3 strategy (scatter, not gather): one CTA per window. Threads 0..94 build
// the 95 candidates (acids then inters, index = scatter order); each candidate
// tests whether it falls inside THIS window's 7^3 bounds (expected hits: ~1-3)
// and, if so, atomicMax's a shared 64-bit slot packed as
//   (candidate_index+1) << 32 | float_bits
// Highest index wins == last write wins == exact scatter ordering. Dropped
// (masked) candidates never scatter. Then 343 threads read their slot and
// write the masked value out. This replaces R2's 95-iteration per-cell sweep
// (~285 instr/thread, issue-bound at 46%) with ~25 instr/thread.
//
// mask is int32 (harness materializes JAX bool as 4-byte ints — R1 lesson).

#define NACID   48
#define KWIN    7
#define PADW    3
#define CELLS   (KWIN * KWIN * KWIN)   // 343
#define NCAND   (2 * NACID - 1)        // 95
#define NTHREADS 352                   // 11 warps >= 343

__global__ __launch_bounds__(NTHREADS)
void lattice_snake_kernel(const float* __restrict__ acids,
                          const int* __restrict__ mask,
                          const int* __restrict__ idx,
                          float* __restrict__ out)
{
    __shared__ unsigned long long win[CELLS];

    const int n = blockIdx.x;          // acid / window index 0..47
    const int b = blockIdx.y;          // batch 0..15
    const int t = threadIdx.x;

    const int*   idxb = idx   + b * NACID * 3;
    const float* ab   = acids + b * NACID;
    const int*   mb   = mask  + b * NACID;

    if (t < CELLS) win[t] = 0ULL;
    __syncthreads();

    // window base in lattice coords: idx2 = 2*idx + 94 (window covers base..base+6)
    // scatter coords carry +PAD: acid -> 2*idx + 97, inter -> idx_j+idx_{j+1} + 97.

    if (t < NCAND) {
        int cx, cy, cz, live;
        float v;
        if (t < NACID) {
            cx = 2 * idxb[3 * t + 0] + 94 + PADW;
            cy = 2 * idxb[3 * t + 1] + 94 + PADW;
            cz = 2 * idxb[3 * t + 2] + 94 + PADW;
            live = mb[t];
            v = ab[t];
        } else {
            const int j = t - NACID;   // 0..46
            cx = idxb[3 * j + 0] + idxb[3 * (j + 1) + 0] + 94 + PADW;
            cy = idxb[3 * j + 1] + idxb[3 * (j + 1) + 1] + 94 + PADW;
            cz = idxb[3 * j + 2] + idxb[3 * (j + 1) + 2] + 94 + PADW;
            live = mb[j + 1];
            v = ab[j] + ab[j + 1] + 1.0f;
        }
        // this CTA's window bounds
        const int dx = cx - (2 * idxb[3 * n + 0] + 94);
        const int dy = cy - (2 * idxb[3 * n + 1] + 94);
        const int dz = cz - (2 * idxb[3 * n + 2] + 94);
        if (live &&
            (unsigned)dx < KWIN && (unsigned)dy < KWIN && (unsigned)dz < KWIN) {
            const int c = dx * 49 + dy * 7 + dz;
            const unsigned long long pk =
                ((unsigned long long)(t + 1) << 32) | (unsigned)__float_as_int(v);
            atomicMax(&win[c], pk);
        }
    }
    __syncthreads();

    if (t < CELLS) {
        const unsigned long long w = win[t];
        float v = (w >> 32) ? __int_as_float((int)(unsigned)w) : 0.0f;
        if (!mb[n]) v = 0.0f;
        out[(b * NACID + n) * CELLS + t] = v;
    }
}

extern "C" void kernel_launch(void* const* d_in, const int* in_sizes, int n_in,
                              void* d_out, int out_size)
{
    const float* acids = (const float*)d_in[0];   // (B, N) float32
    const int*   mask  = (const int*)d_in[1];     // (B, N) bool -> int32
    const int*   idx   = (const int*)d_in[2];     // (B, N, 3) int32
    float*       out   = (float*)d_out;           // (B, N, 7,7,7, 1) float32

    dim3 grid(NACID, 16);
    lattice_snake_kernel<<<grid, NTHREADS>>>(acids, mask, idx, out);
}